// round 4
// baseline (speedup 1.0000x reference)
#include <cuda_runtime.h>

#define N_MAX 4096
#define D 1024
#define THR 0.25f
#define ROUNDS 4
#define K_TOP 16
#define GRP 32            // group window size
#define T_LANE 6          // per-lane sorted candidates in group build
#define FULLMASK 0xFFFFFFFFu

#define BARRIER() asm volatile("bar.sync 0;" ::: "memory")

// ---------------- device state (static scratch; no runtime allocation) ----------------
__device__ float g_emb[N_MAX * D];
__device__ float g_ec[N_MAX * D];
__device__ float g_sim[(size_t)N_MAX * N_MAX];
__device__ unsigned long long g_topkey[N_MAX * K_TOP];
__device__ int g_idx[N_MAX];
__device__ int g_partner[N_MAX];
__device__ unsigned char g_alive[N_MAX];
__device__ int g_m;
__device__ int g_done;

// ---------------- init ----------------
__global__ void k_init(const float* __restrict__ in) {
    int i = blockIdx.x * blockDim.x + threadIdx.x;
    int stride = gridDim.x * blockDim.x;
    for (int t = i; t < N_MAX * D; t += stride) g_emb[t] = in[t];
    if (i < N_MAX) g_alive[i] = 1;
    if (i == 0) g_done = 0;
}

// ---------------- compact alive indices (order-preserving) ----------------
__global__ void k_compact() {  // <<<1,1024>>>
    if (g_done) return;
    __shared__ int wsum[32];
    int tid = threadIdx.x;
    int base = tid * 4;
    int f0 = g_alive[base + 0];
    int f1 = g_alive[base + 1];
    int f2 = g_alive[base + 2];
    int f3 = g_alive[base + 3];
    int cnt = f0 + f1 + f2 + f3;
    int lane = tid & 31, wid = tid >> 5;
    int inc = cnt;
#pragma unroll
    for (int off = 1; off < 32; off <<= 1) {
        int u = __shfl_up_sync(FULLMASK, inc, off);
        if (lane >= off) inc += u;
    }
    if (lane == 31) wsum[wid] = inc;
    __syncthreads();
    if (wid == 0) {
        int v = wsum[lane];
#pragma unroll
        for (int off = 1; off < 32; off <<= 1) {
            int u = __shfl_up_sync(FULLMASK, v, off);
            if (lane >= off) v += u;
        }
        wsum[lane] = v;
    }
    __syncthreads();
    int ex = inc - cnt + (wid ? wsum[wid - 1] : 0);
    if (f0) g_idx[ex++] = base + 0;
    if (f1) g_idx[ex++] = base + 1;
    if (f2) g_idx[ex++] = base + 2;
    if (f3) g_idx[ex++] = base + 3;
    if (tid == 0) g_m = wsum[31];
}

// ---------------- gather compacted rows (zero-pad to N_MAX) ----------------
__global__ void k_gather() {  // <<<N_MAX, 256>>>
    if (g_done) return;
    int row = blockIdx.x;
    int m = g_m;
    float4* d = (float4*)(g_ec + (size_t)row * D);
    if (row < m) {
        const float4* s = (const float4*)(g_emb + (size_t)g_idx[row] * D);
        d[threadIdx.x] = s[threadIdx.x];
    } else {
        d[threadIdx.x] = make_float4(0.f, 0.f, 0.f, 0.f);
    }
}

// ---------------- fp32 SGEMM: sim[a][b] = dot(ec[a],ec[b])/D, upper-triangle tiles ----------------
__global__ void __launch_bounds__(256) k_gemm() {  // grid (32,32), 256 thr
    if (g_done) return;
    int m = g_m;
    int by = blockIdx.y;
    int bx = blockIdx.x;
    if (bx < by) return;
    if (by * 128 >= m || bx * 128 >= m) return;

    __shared__ float As[16][132];
    __shared__ float Bs[16][132];
    int tid = threadIdx.x;
    int lr = tid >> 2;
    int lq = tid & 3;
    int ty = tid >> 4;
    int tx = tid & 15;

    const float* Abase = g_ec + (size_t)(by * 128) * D;
    const float* Bbase = g_ec + (size_t)(bx * 128) * D;

    float acc[8][8] = {};

    for (int k0 = 0; k0 < D; k0 += 16) {
        float4 av0 = *(const float4*)(Abase + (size_t)lr * D + k0 + lq * 4);
        float4 av1 = *(const float4*)(Abase + (size_t)(lr + 64) * D + k0 + lq * 4);
        float4 bv0 = *(const float4*)(Bbase + (size_t)lr * D + k0 + lq * 4);
        float4 bv1 = *(const float4*)(Bbase + (size_t)(lr + 64) * D + k0 + lq * 4);
        __syncthreads();
        As[lq * 4 + 0][lr] = av0.x; As[lq * 4 + 1][lr] = av0.y;
        As[lq * 4 + 2][lr] = av0.z; As[lq * 4 + 3][lr] = av0.w;
        As[lq * 4 + 0][lr + 64] = av1.x; As[lq * 4 + 1][lr + 64] = av1.y;
        As[lq * 4 + 2][lr + 64] = av1.z; As[lq * 4 + 3][lr + 64] = av1.w;
        Bs[lq * 4 + 0][lr] = bv0.x; Bs[lq * 4 + 1][lr] = bv0.y;
        Bs[lq * 4 + 2][lr] = bv0.z; Bs[lq * 4 + 3][lr] = bv0.w;
        Bs[lq * 4 + 0][lr + 64] = bv1.x; Bs[lq * 4 + 1][lr + 64] = bv1.y;
        Bs[lq * 4 + 2][lr + 64] = bv1.z; Bs[lq * 4 + 3][lr + 64] = bv1.w;
        __syncthreads();
#pragma unroll
        for (int kk = 0; kk < 16; ++kk) {
            float ra[8], rb[8];
#pragma unroll
            for (int i = 0; i < 8; ++i) ra[i] = As[kk][ty * 8 + i];
#pragma unroll
            for (int j = 0; j < 8; ++j) rb[j] = Bs[kk][tx * 8 + j];
#pragma unroll
            for (int i = 0; i < 8; ++i)
#pragma unroll
                for (int j = 0; j < 8; ++j) acc[i][j] += ra[i] * rb[j];
        }
    }

    const float s = 1.0f / (float)D;
#pragma unroll
    for (int i = 0; i < 8; ++i) {
        int a = by * 128 + ty * 8 + i;
        float* out = g_sim + (size_t)a * N_MAX + bx * 128 + tx * 8;
#pragma unroll
        for (int j = 0; j < 8; ++j) out[j] = acc[i][j] * s;
    }
}

// ---------------- per-row top-K (packed keys; first-occurrence argmax tie-break) ----------------
__global__ void k_topk() {  // <<<N_MAX/8, 256>>>
    if (g_done) return;
    int m = g_m;
    int warp = threadIdx.x >> 5;
    int lane = threadIdx.x & 31;
    int a = blockIdx.x * 8 + warp;
    if (a >= m) return;

    unsigned long long loc[K_TOP];
#pragma unroll
    for (int t = 0; t < K_TOP; ++t) loc[t] = 0ULL;

    const float* row = g_sim + (size_t)a * N_MAX;
    for (int b = a + 1 + lane; b < m; b += 32) {
        unsigned int vb = __float_as_uint(row[b]);
        unsigned long long key =
            ((unsigned long long)vb << 32) | (unsigned int)(0xFFFFFFFFu - (unsigned)b);
        if (key > loc[K_TOP - 1]) {
            loc[K_TOP - 1] = key;
#pragma unroll
            for (int t = K_TOP - 1; t > 0; --t) {
                if (loc[t] > loc[t - 1]) {
                    unsigned long long tmp = loc[t];
                    loc[t] = loc[t - 1];
                    loc[t - 1] = tmp;
                }
            }
        }
    }

    unsigned long long mykey = 0ULL;
#pragma unroll
    for (int s = 0; s < K_TOP; ++s) {
        unsigned long long h = loc[0];
#pragma unroll
        for (int off = 16; off > 0; off >>= 1) {
            unsigned long long o = __shfl_xor_sync(FULLMASK, h, off);
            if (o > h) h = o;
        }
        if (lane == s) mykey = h;
        unsigned ball = __ballot_sync(FULLMASK, (loc[0] == h) && (h != 0ULL));
        int wl = ball ? (__ffs(ball) - 1) : -1;
        if (lane == wl) {
#pragma unroll
            for (int t = 0; t < K_TOP - 1; ++t) loc[t] = loc[t + 1];
            loc[K_TOP - 1] = 0ULL;
        }
    }
    if (lane < K_TOP) g_topkey[a * K_TOP + lane] = mykey;
}

// ======================= sequential greedy matching =======================
// 1 block / 1024 threads. Warp 0 drives rows in order. When a row's global
// top-16 list is exhausted (stale vs consumption), the whole block rebuilds
// fresh availability-filtered top-32 lists for the next 32 rows (one warp per
// row). Lists stay sufficient for the 32-row window (<=31 consumptions).
// Rare unresolvable rows fall back to a block-wide full-row rescan.

struct SeqShared {
    unsigned int consumed[N_MAX / 32];
    unsigned long long gkeys[GRP * (GRP + 1)];  // stride GRP+1
    int gL[GRP];
    int gComplete[GRP];
    unsigned long long partial[32];
    int cmd;   // 1=group build, 2=row rescan, 3=exit
    int row;
};

__device__ __forceinline__ unsigned long long warpmax_u64(unsigned long long v) {
#pragma unroll
    for (int off = 16; off > 0; off >>= 1) {
        unsigned long long o = __shfl_xor_sync(FULLMASK, v, off);
        if (o > v) v = o;
    }
    return v;
}

// Build exact availability-filtered sorted top-L (L<=32) for row r into slot.
__device__ void build_group_row(SeqShared* sh, int r, int m, int slot) {
    int lane = threadIdx.x & 31;
    volatile unsigned int* consumed = sh->consumed;

    bool dead = (r >= m) || ((consumed[r >> 5] >> (r & 31)) & 1u);
    if (dead) {
        if (lane == 0) { sh->gL[slot] = 0; sh->gComplete[slot] = 1; }
        return;
    }

    unsigned long long loc[T_LANE];
#pragma unroll
    for (int t = 0; t < T_LANE; ++t) loc[t] = 0ULL;
    unsigned long long eb = 0ULL;  // max dropped key (unknown-tail bound)

    const float* row = g_sim + (size_t)r * N_MAX;
    for (int b = r + 1 + lane; b < m; b += 32) {
        if ((consumed[b >> 5] >> (b & 31)) & 1u) continue;
        unsigned long long key =
            ((unsigned long long)__float_as_uint(row[b]) << 32) |
            (unsigned int)(0xFFFFFFFFu - (unsigned)b);
        if (key > loc[T_LANE - 1]) {
            if (loc[T_LANE - 1] > eb) eb = loc[T_LANE - 1];
            loc[T_LANE - 1] = key;
#pragma unroll
            for (int t = T_LANE - 1; t > 0; --t) {
                if (loc[t] > loc[t - 1]) {
                    unsigned long long tmp = loc[t];
                    loc[t] = loc[t - 1];
                    loc[t - 1] = tmp;
                }
            }
        } else if (key > eb) {
            eb = key;
        }
    }

    unsigned long long B = warpmax_u64(eb);

    int hp = 0;
    int L = 0;
    int truncated = 0;
    for (int step = 0; step < GRP; ++step) {
        unsigned long long hv = (hp < T_LANE) ? loc[hp] : 0ULL;
        unsigned long long h = warpmax_u64(hv);
        if (h == 0ULL) break;                 // known candidates exhausted
        if (h < B) { truncated = 1; break; }  // an unknown (dropped) key may exceed h
        unsigned ball = __ballot_sync(FULLMASK, hv == h);
        if (lane == __ffs(ball) - 1) hp++;
        if (lane == 0) sh->gkeys[slot * (GRP + 1) + step] = h;
        L++;
    }
    if (lane == 0) {
        sh->gL[slot] = L;
        sh->gComplete[slot] = (!truncated && B == 0ULL) ? 1 : 0;
    }
}

// Block-wide fallback: this thread's slice contribution to argmax over available.
__device__ unsigned long long rescan_slice(SeqShared* sh, int a, int m) {
    volatile unsigned int* consumed = sh->consumed;
    unsigned long long best = 0ULL;
    const float* row = g_sim + (size_t)a * N_MAX;
    for (int bb = a + 1 + threadIdx.x; bb < m; bb += 1024) {
        if (!((consumed[bb >> 5] >> (bb & 31)) & 1u)) {
            unsigned long long key =
                ((unsigned long long)__float_as_uint(row[bb]) << 32) |
                (unsigned int)(0xFFFFFFFFu - (unsigned)bb);
            if (key > best) best = key;
        }
    }
    return warpmax_u64(best);
}

__global__ void __launch_bounds__(1024, 1) k_seq3() {  // <<<1,1024>>>
    __shared__ SeqShared sh;

    int tid = threadIdx.x, lane = tid & 31, wid = tid >> 5;

    if (g_done) {
        for (int a = tid; a < N_MAX; a += 1024) g_partner[a] = -1;
        return;
    }
    int m = g_m;
    for (int t = tid; t < N_MAX / 32; t += 1024) sh.consumed[t] = 0u;
    __syncthreads();

    volatile unsigned int* consumed = sh.consumed;

    if (wid == 0) {
        // ---------------- warp 0: sequential driver ----------------
        int merges = 0;
        int grp_base = -1000000;
        unsigned long long kcur =
            (lane < K_TOP && 0 < m) ? g_topkey[0 * K_TOP + lane] : 0ULL;
        unsigned long long knext =
            (lane < K_TOP && 1 < m) ? g_topkey[1 * K_TOP + lane] : 0ULL;

        for (int a = 0; a < m; ++a) {
            unsigned long long knext2 =
                (lane < K_TOP && a + 2 < m) ? g_topkey[(size_t)(a + 2) * K_TOP + lane] : 0ULL;

            bool ca = (consumed[a >> 5] >> (a & 31)) & 1u;  // lane-uniform
            int partner = -1;
            if (!ca) {
                bool in_group = (grp_base >= 0) && (a < grp_base + GRP);
                bool resolved = false;

                if (!in_group) {
                    // ---- global K16 list path ----
                    int b = (int)(0xFFFFFFFFu - (unsigned int)(kcur & 0xFFFFFFFFull));
                    bool valid = (lane < K_TOP) && (kcur != 0ULL);
                    bool avail = valid && !((consumed[b >> 5] >> (b & 31)) & 1u);
                    unsigned ba = __ballot_sync(FULLMASK, avail);
                    unsigned bz = __ballot_sync(FULLMASK, (lane < K_TOP) && (kcur == 0ULL));
                    if (ba) {
                        unsigned long long kf = __shfl_sync(FULLMASK, kcur, __ffs(ba) - 1);
                        float v = __uint_as_float((unsigned int)(kf >> 32));
                        if (v >= THR)
                            partner = (int)(0xFFFFFFFFu - (unsigned int)(kf & 0xFFFFFFFFull));
                        resolved = true;
                    } else if (bz || (m - 1 - a) <= K_TOP) {
                        resolved = true;  // list complete; nothing available
                    } else {
                        // ---- group rebuild for rows [a, a+32) ----
                        if (lane == 0) { sh.cmd = 1; sh.row = a; }
                        BARRIER();                       // engage all warps
                        build_group_row(&sh, a, m, 0);   // warp0 builds slot 0
                        BARRIER();                       // lists ready
                        grp_base = a;
                        in_group = true;
                    }
                }

                if (in_group && !resolved) {
                    int p = a - grp_base;
                    int L = sh.gL[p];
                    unsigned long long k =
                        (lane < L) ? sh.gkeys[p * (GRP + 1) + lane] : 0ULL;
                    int b = (int)(0xFFFFFFFFu - (unsigned int)(k & 0xFFFFFFFFull));
                    bool avail = (k != 0ULL) && !((consumed[b >> 5] >> (b & 31)) & 1u);
                    unsigned ba = __ballot_sync(FULLMASK, avail);
                    if (ba) {
                        unsigned long long kf = __shfl_sync(FULLMASK, k, __ffs(ba) - 1);
                        float v = __uint_as_float((unsigned int)(kf >> 32));
                        if (v >= THR)
                            partner = (int)(0xFFFFFFFFu - (unsigned int)(kf & 0xFFFFFFFFull));
                        resolved = true;
                    } else if (sh.gComplete[p]) {
                        resolved = true;
                    }
                    if (!resolved) {
                        // ---- rare: block-wide full-row rescan ----
                        if (lane == 0) { sh.cmd = 2; sh.row = a; }
                        BARRIER();
                        unsigned long long w0 = rescan_slice(&sh, a, m);
                        if (lane == 0) sh.partial[0] = w0;
                        BARRIER();
                        unsigned long long p2 = sh.partial[lane];
                        p2 = warpmax_u64(p2);
                        if (p2 != 0ULL) {
                            float v = __uint_as_float((unsigned int)(p2 >> 32));
                            if (v >= THR)
                                partner = (int)(0xFFFFFFFFu - (unsigned int)(p2 & 0xFFFFFFFFull));
                        }
                        resolved = true;
                    }
                }
            }
            if (partner >= 0) {
                ++merges;
                if (lane == 0) consumed[partner >> 5] |= (1u << (partner & 31));
            }
            if (lane == 0) g_partner[a] = partner;
            __syncwarp();
            kcur = knext;
            knext = knext2;
        }
        if (lane == 0) sh.cmd = 3;
        BARRIER();  // release workers to exit
        for (int a = m + lane; a < N_MAX; a += 32) g_partner[a] = -1;
        if (lane == 0) {
            if (merges == 0 || (m - merges) <= 1) g_done = 1;
        }
    } else {
        // ---------------- warps 1..31: command servers ----------------
        while (true) {
            BARRIER();
            int cmd = sh.cmd;
            if (cmd == 3) break;
            if (cmd == 1) {
                build_group_row(&sh, sh.row + wid, m, wid);
            } else {
                unsigned long long w = rescan_slice(&sh, sh.row, m);
                if (lane == 0) sh.partial[wid] = w;
            }
            BARRIER();
        }
    }
}

// ---------------- apply merges: fuse initiator, zero+kill partner ----------------
__global__ void k_apply() {  // <<<N_MAX, 256>>>
    int a = blockIdx.x;
    int p = g_partner[a];
    if (p < 0) return;
    int gi = g_idx[a];
    int gj = g_idx[p];
    float4* vi = (float4*)(g_emb + (size_t)gi * D);
    float4* vj = (float4*)(g_emb + (size_t)gj * D);
    int t = threadIdx.x;
    float4 x = vi[t];
    float4 y = vj[t];
    x.x = fminf(x.x + y.x, 1.0f);
    x.y = fminf(x.y + y.y, 1.0f);
    x.z = fminf(x.z + y.z, 1.0f);
    x.w = fminf(x.w + y.w, 1.0f);
    vi[t] = x;
    vj[t] = make_float4(0.f, 0.f, 0.f, 0.f);
    if (t == 0) g_alive[gj] = 0;
}

// ---------------- write output: emb then alive (as float) ----------------
__global__ void k_output(float* __restrict__ out, int out_size) {
    int i = blockIdx.x * blockDim.x + threadIdx.x;
    int stride = gridDim.x * blockDim.x;
    for (int t = i; t < N_MAX * D; t += stride)
        if (t < out_size) out[t] = g_emb[t];
    for (int r = i; r < N_MAX; r += stride) {
        int o = N_MAX * D + r;
        if (o < out_size) out[o] = g_alive[r] ? 1.0f : 0.0f;
    }
}

extern "C" void kernel_launch(void* const* d_in, const int* in_sizes, int n_in,
                              void* d_out, int out_size) {
    const float* in = (const float*)d_in[0];
    k_init<<<4096, 256>>>(in);
    for (int r = 0; r < ROUNDS; ++r) {
        k_compact<<<1, 1024>>>();
        k_gather<<<N_MAX, 256>>>();
        dim3 grid(32, 32);
        k_gemm<<<grid, 256>>>();
        k_topk<<<N_MAX / 8, 256>>>();
        k_seq3<<<1, 1024>>>();
        k_apply<<<N_MAX, 256>>>();
    }
    k_output<<<4096, 256>>>((float*)d_out, out_size);
}

// round 5
// speedup vs baseline: 2.7661x; 2.7661x over previous
#include <cuda_runtime.h>

#define N_MAX 4096
#define D 1024
#define THR 0.25f
#define ROUNDS 4
#define W_SLOTS 512          // rows built per pass
#define T_LANE 6             // per-lane sorted candidates in build
#define FULLMASK 0xFFFFFFFFu

// ---------------- device state (static scratch; no runtime allocation) ----------------
__device__ float g_emb[N_MAX * D];
__device__ float g_ec[N_MAX * D];
__device__ float g_sim[(size_t)N_MAX * N_MAX];
__device__ unsigned long long g_fresh[W_SLOTS * 32];   // per-slot sorted top-L keys
__device__ int g_freshmeta[W_SLOTS];                   // L | complete<<16
__device__ unsigned int g_consumed[N_MAX / 32];
__device__ int g_idx[N_MAX];
__device__ int g_partner[N_MAX];
__device__ unsigned char g_alive[N_MAX];
__device__ int g_m;
__device__ int g_done;
__device__ int g_frontier;
__device__ int g_merges;
__device__ int g_ticket;

__device__ __forceinline__ unsigned long long warpmax_u64(unsigned long long v) {
#pragma unroll
    for (int off = 16; off > 0; off >>= 1) {
        unsigned long long o = __shfl_xor_sync(FULLMASK, v, off);
        if (o > v) v = o;
    }
    return v;
}

// ---------------- init ----------------
__global__ void k_init(const float* __restrict__ in) {
    int i = blockIdx.x * blockDim.x + threadIdx.x;
    int stride = gridDim.x * blockDim.x;
    for (int t = i; t < N_MAX * D; t += stride) g_emb[t] = in[t];
    if (i < N_MAX) g_alive[i] = 1;
    if (i == 0) g_done = 0;
}

// ---------------- compact alive indices + per-round state reset ----------------
__global__ void k_compact() {  // <<<1,1024>>>
    int tid = threadIdx.x;
    if (g_done) {
#pragma unroll
        for (int q = 0; q < 4; ++q) g_partner[tid * 4 + q] = -1;
        return;
    }
#pragma unroll
    for (int q = 0; q < 4; ++q) g_partner[tid * 4 + q] = -1;
    if (tid < N_MAX / 32) g_consumed[tid] = 0u;
    if (tid == 0) { g_frontier = 0; g_merges = 0; g_ticket = 0; }

    __shared__ int wsum[32];
    int base = tid * 4;
    int f0 = g_alive[base + 0];
    int f1 = g_alive[base + 1];
    int f2 = g_alive[base + 2];
    int f3 = g_alive[base + 3];
    int cnt = f0 + f1 + f2 + f3;
    int lane = tid & 31, wid = tid >> 5;
    int inc = cnt;
#pragma unroll
    for (int off = 1; off < 32; off <<= 1) {
        int u = __shfl_up_sync(FULLMASK, inc, off);
        if (lane >= off) inc += u;
    }
    if (lane == 31) wsum[wid] = inc;
    __syncthreads();
    if (wid == 0) {
        int v = wsum[lane];
#pragma unroll
        for (int off = 1; off < 32; off <<= 1) {
            int u = __shfl_up_sync(FULLMASK, v, off);
            if (lane >= off) v += u;
        }
        wsum[lane] = v;
    }
    __syncthreads();
    int ex = inc - cnt + (wid ? wsum[wid - 1] : 0);
    if (f0) g_idx[ex++] = base + 0;
    if (f1) g_idx[ex++] = base + 1;
    if (f2) g_idx[ex++] = base + 2;
    if (f3) g_idx[ex++] = base + 3;
    if (tid == 0) g_m = wsum[31];
}

// ---------------- gather compacted rows (zero-pad to N_MAX) ----------------
__global__ void k_gather() {  // <<<N_MAX, 256>>>
    if (g_done) return;
    int row = blockIdx.x;
    int m = g_m;
    float4* d = (float4*)(g_ec + (size_t)row * D);
    if (row < m) {
        const float4* s = (const float4*)(g_emb + (size_t)g_idx[row] * D);
        d[threadIdx.x] = s[threadIdx.x];
    } else {
        d[threadIdx.x] = make_float4(0.f, 0.f, 0.f, 0.f);
    }
}

// ---------------- fp32 SGEMM: sim[a][b] = dot(ec[a],ec[b])/D, upper-triangle tiles ----------------
__global__ void __launch_bounds__(256) k_gemm() {  // grid (32,32), 256 thr
    if (g_done) return;
    int m = g_m;
    int by = blockIdx.y;
    int bx = blockIdx.x;
    if (bx < by) return;
    if (by * 128 >= m || bx * 128 >= m) return;

    __shared__ __align__(16) float As[16][132];
    __shared__ __align__(16) float Bs[16][132];
    int tid = threadIdx.x;
    int lr = tid >> 2;
    int lq = tid & 3;
    int ty = tid >> 4;
    int tx = tid & 15;

    const float* Abase = g_ec + (size_t)(by * 128) * D;
    const float* Bbase = g_ec + (size_t)(bx * 128) * D;

    float acc[8][8] = {};

    for (int k0 = 0; k0 < D; k0 += 16) {
        float4 av0 = *(const float4*)(Abase + (size_t)lr * D + k0 + lq * 4);
        float4 av1 = *(const float4*)(Abase + (size_t)(lr + 64) * D + k0 + lq * 4);
        float4 bv0 = *(const float4*)(Bbase + (size_t)lr * D + k0 + lq * 4);
        float4 bv1 = *(const float4*)(Bbase + (size_t)(lr + 64) * D + k0 + lq * 4);
        __syncthreads();
        As[lq * 4 + 0][lr] = av0.x; As[lq * 4 + 1][lr] = av0.y;
        As[lq * 4 + 2][lr] = av0.z; As[lq * 4 + 3][lr] = av0.w;
        As[lq * 4 + 0][lr + 64] = av1.x; As[lq * 4 + 1][lr + 64] = av1.y;
        As[lq * 4 + 2][lr + 64] = av1.z; As[lq * 4 + 3][lr + 64] = av1.w;
        Bs[lq * 4 + 0][lr] = bv0.x; Bs[lq * 4 + 1][lr] = bv0.y;
        Bs[lq * 4 + 2][lr] = bv0.z; Bs[lq * 4 + 3][lr] = bv0.w;
        Bs[lq * 4 + 0][lr + 64] = bv1.x; Bs[lq * 4 + 1][lr + 64] = bv1.y;
        Bs[lq * 4 + 2][lr + 64] = bv1.z; Bs[lq * 4 + 3][lr + 64] = bv1.w;
        __syncthreads();
#pragma unroll
        for (int kk = 0; kk < 16; ++kk) {
            float4 a0 = *(const float4*)&As[kk][ty * 8];
            float4 a1 = *(const float4*)&As[kk][ty * 8 + 4];
            float4 b0 = *(const float4*)&Bs[kk][tx * 8];
            float4 b1 = *(const float4*)&Bs[kk][tx * 8 + 4];
            float ra[8] = {a0.x, a0.y, a0.z, a0.w, a1.x, a1.y, a1.z, a1.w};
            float rb[8] = {b0.x, b0.y, b0.z, b0.w, b1.x, b1.y, b1.z, b1.w};
#pragma unroll
            for (int i = 0; i < 8; ++i)
#pragma unroll
                for (int j = 0; j < 8; ++j) acc[i][j] += ra[i] * rb[j];
        }
    }

    const float s = 1.0f / (float)D;
#pragma unroll
    for (int i = 0; i < 8; ++i) {
        int a = by * 128 + ty * 8 + i;
        float* out = g_sim + (size_t)a * N_MAX + bx * 128 + tx * 8;
#pragma unroll
        for (int j = 0; j < 8; ++j) out[j] = acc[i][j] * s;
    }
}

// ---------------- per-pass fresh list build (warp-collective, exact sorted top-L) ----------------
__device__ void build_fresh(int r, int m, int slot, const unsigned int* cons) {
    int lane = threadIdx.x & 31;
    if (r >= m) return;  // slot never read by sweep
    bool dead = (cons[r >> 5] >> (r & 31)) & 1u;
    if (dead) {
        if (lane == 0) g_freshmeta[slot] = (1 << 16);  // L=0, complete
        return;
    }
    unsigned long long loc[T_LANE];
#pragma unroll
    for (int t = 0; t < T_LANE; ++t) loc[t] = 0ULL;
    unsigned long long eb = 0ULL;  // max evicted key

    const float* row = g_sim + (size_t)r * N_MAX;
    for (int b = r + 1 + lane; b < m; b += 32) {
        if ((cons[b >> 5] >> (b & 31)) & 1u) continue;
        unsigned long long key =
            ((unsigned long long)__float_as_uint(row[b]) << 32) |
            (unsigned int)(0xFFFFFFFFu - (unsigned)b);
        if (key > loc[T_LANE - 1]) {
            if (loc[T_LANE - 1] > eb) eb = loc[T_LANE - 1];
            loc[T_LANE - 1] = key;
#pragma unroll
            for (int t = T_LANE - 1; t > 0; --t) {
                if (loc[t] > loc[t - 1]) {
                    unsigned long long tmp = loc[t];
                    loc[t] = loc[t - 1];
                    loc[t - 1] = tmp;
                }
            }
        } else if (key > eb) {
            eb = key;
        }
    }

    unsigned long long B = warpmax_u64(eb);
    int hp = 0, L = 0, complete = 0;
    for (int step = 0; step < 32; ++step) {
        unsigned long long hv = (hp < T_LANE) ? loc[hp] : 0ULL;
        unsigned long long h = warpmax_u64(hv);
        if (h == 0ULL) { if (B == 0ULL) complete = 1; break; }
        if (h < B) break;  // unknown evicted key could outrank h
        unsigned ball = __ballot_sync(FULLMASK, hv == h);
        if (lane == __ffs(ball) - 1) hp++;
        if (lane == 0) g_fresh[slot * 32 + step] = h;
        L++;
    }
    if (lane == 0) g_freshmeta[slot] = L | (complete << 16);
}

// ---------------- single-warp frontier sweep over fresh lists ----------------
__device__ void sweep_warp(int m, int F, unsigned int* cons /*shared*/) {
    int lane = threadIdx.x;  // warp 0 only
    int Wend = (F + W_SLOTS < m) ? (F + W_SLOTS) : m;
    int n = Wend - F;

    unsigned long long kA = (n > 0 && lane < 32) ? g_fresh[0 * 32 + lane] : 0ULL;
    int mA = (n > 0) ? g_freshmeta[0] : 0;
    unsigned long long kB = (n > 1) ? g_fresh[1 * 32 + lane] : 0ULL;
    int mB = (n > 1) ? g_freshmeta[1] : 0;

    int merges = 0;
    int stop = -1;

    for (int a = F; a < Wend; ++a) {
        int slot = a - F;
        unsigned long long kC = (slot + 2 < n) ? g_fresh[(size_t)(slot + 2) * 32 + lane] : 0ULL;
        int mC = (slot + 2 < n) ? g_freshmeta[slot + 2] : 0;

        bool ca = (cons[a >> 5] >> (a & 31)) & 1u;  // lane-uniform
        int partner = -1;
        if (!ca) {
            int L = mA & 0xFFFF;
            int comp = mA >> 16;
            unsigned long long k = (lane < L) ? kA : 0ULL;
            int b = (int)((0xFFFFFFFFu - (unsigned int)(k & 0xFFFFFFFFull)) & (N_MAX - 1));
            bool avail = (k != 0ULL) && !((cons[b >> 5] >> (b & 31)) & 1u);
            unsigned ba = __ballot_sync(FULLMASK, avail);
            if (ba) {
                unsigned long long kf = __shfl_sync(FULLMASK, kA, __ffs(ba) - 1);
                float v = __uint_as_float((unsigned int)(kf >> 32));
                if (v >= THR)
                    partner = (int)(0xFFFFFFFFu - (unsigned int)(kf & 0xFFFFFFFFull));
            } else if (!comp) {
                stop = a;  // stale list, rebuild next pass
            }
        }
        if (stop >= 0) break;
        if (partner >= 0) {
            ++merges;
            if (lane == 0) cons[partner >> 5] |= (1u << (partner & 31));
        }
        if (lane == 0) g_partner[a] = partner;
        __syncwarp();
        kA = kB; mA = mB; kB = kC; mB = mC;
    }

    int newF = (stop >= 0) ? stop : Wend;
    for (int w = lane; w < N_MAX / 32; w += 32) g_consumed[w] = cons[w];
    if (lane == 0) {
        g_frontier = newF;
        g_merges += merges;
        if (newF == m) {
            int tm = g_merges;
            if (tm == 0 || (m - tm) <= 1) g_done = 1;
        }
    }
}

// ---------------- one pass: parallel fresh builds + (last block) sequential sweep ----------------
__global__ void __launch_bounds__(256) k_pass() {  // <<<W_SLOTS/8, 256>>>
    int m = *(volatile int*)&g_m;
    int F = *(volatile int*)&g_frontier;
    if (*(volatile int*)&g_done || F >= m) return;

    __shared__ unsigned int s_cons[N_MAX / 32];
    __shared__ int s_last;
    int tid = threadIdx.x;
    if (tid < N_MAX / 32) s_cons[tid] = g_consumed[tid];
    __syncthreads();

    int warp = tid >> 5;
    int slot = blockIdx.x * 8 + warp;
    build_fresh(F + slot, m, slot, s_cons);

    __threadfence();   // release this thread's list writes
    __syncthreads();
    if (tid == 0) s_last = (atomicAdd(&g_ticket, 1) == (int)gridDim.x - 1);
    __syncthreads();
    if (!s_last) return;

    __threadfence();   // acquire other blocks' list writes
    if (warp == 0) sweep_warp(m, F, s_cons);
    __syncthreads();
    if (tid == 0) g_ticket = 0;
}

// ---------------- exact finish net: block-rescan remaining rows (normally a no-op) ------------
__global__ void __launch_bounds__(1024, 1) k_finish() {  // <<<1,1024>>>
    int m = g_m;
    int F = g_frontier;
    if (g_done || F >= m) return;

    __shared__ unsigned int cons[N_MAX / 32];
    __shared__ unsigned long long partial[32];
    int tid = threadIdx.x, lane = tid & 31, wid = tid >> 5;
    if (tid < N_MAX / 32) cons[tid] = g_consumed[tid];
    __syncthreads();

    int merges = 0;  // maintained by thread 0 only
    for (int a = F; a < m; ++a) {
        bool ca = (cons[a >> 5] >> (a & 31)) & 1u;  // uniform
        unsigned long long best = 0ULL;
        if (!ca) {
            const float* row = g_sim + (size_t)a * N_MAX;
            for (int b = a + 1 + tid; b < m; b += 1024) {
                if (!((cons[b >> 5] >> (b & 31)) & 1u)) {
                    unsigned long long key =
                        ((unsigned long long)__float_as_uint(row[b]) << 32) |
                        (unsigned int)(0xFFFFFFFFu - (unsigned)b);
                    if (key > best) best = key;
                }
            }
        }
        best = warpmax_u64(best);
        if (lane == 0) partial[wid] = best;
        __syncthreads();
        if (wid == 0) {
            unsigned long long p = warpmax_u64(partial[lane]);
            if (lane == 0) {
                int partner = -1;
                if (!ca && p != 0ULL) {
                    float v = __uint_as_float((unsigned int)(p >> 32));
                    if (v >= THR)
                        partner = (int)(0xFFFFFFFFu - (unsigned int)(p & 0xFFFFFFFFull));
                }
                g_partner[a] = partner;
                if (partner >= 0) {
                    ++merges;
                    cons[partner >> 5] |= (1u << (partner & 31));
                }
            }
        }
        __syncthreads();
    }
    if (tid < N_MAX / 32) g_consumed[tid] = cons[tid];
    if (tid == 0) {
        g_frontier = m;
        g_merges += merges;
        int tm = g_merges;
        if (tm == 0 || (m - tm) <= 1) g_done = 1;
    }
}

// ---------------- apply merges: fuse initiator, zero+kill partner ----------------
__global__ void k_apply() {  // <<<N_MAX, 256>>>
    int a = blockIdx.x;
    int p = g_partner[a];
    if (p < 0) return;
    int gi = g_idx[a];
    int gj = g_idx[p];
    float4* vi = (float4*)(g_emb + (size_t)gi * D);
    float4* vj = (float4*)(g_emb + (size_t)gj * D);
    int t = threadIdx.x;
    float4 x = vi[t];
    float4 y = vj[t];
    x.x = fminf(x.x + y.x, 1.0f);
    x.y = fminf(x.y + y.y, 1.0f);
    x.z = fminf(x.z + y.z, 1.0f);
    x.w = fminf(x.w + y.w, 1.0f);
    vi[t] = x;
    vj[t] = make_float4(0.f, 0.f, 0.f, 0.f);
    if (t == 0) g_alive[gj] = 0;
}

// ---------------- write output: emb then alive (as float) ----------------
__global__ void k_output(float* __restrict__ out, int out_size) {
    int i = blockIdx.x * blockDim.x + threadIdx.x;
    int stride = gridDim.x * blockDim.x;
    for (int t = i; t < N_MAX * D; t += stride)
        if (t < out_size) out[t] = g_emb[t];
    for (int r = i; r < N_MAX; r += stride) {
        int o = N_MAX * D + r;
        if (o < out_size) out[o] = g_alive[r] ? 1.0f : 0.0f;
    }
}

extern "C" void kernel_launch(void* const* d_in, const int* in_sizes, int n_in,
                              void* d_out, int out_size) {
    const float* in = (const float*)d_in[0];
    static const int pass_budget[ROUNDS] = {12, 32, 20, 12};
    k_init<<<4096, 256>>>(in);
    for (int r = 0; r < ROUNDS; ++r) {
        k_compact<<<1, 1024>>>();
        k_gather<<<N_MAX, 256>>>();
        dim3 grid(32, 32);
        k_gemm<<<grid, 256>>>();
        for (int p = 0; p < pass_budget[r]; ++p)
            k_pass<<<W_SLOTS / 8, 256>>>();
        k_finish<<<1, 1024>>>();
        k_apply<<<N_MAX, 256>>>();
    }
    k_output<<<4096, 256>>>((float*)d_out, out_size);
}